// round 4
// baseline (speedup 1.0000x reference)
#include <cuda_runtime.h>
#include <cuda_bf16.h>

#define B       16384
#define D       1024
#define DV      (D / 4)          // 256 float4 per row
#define N_PER   8
#define G       (B / N_PER)      // 2048
#define MARGIN  0.5f
#define NBLK    444              // 148 SMs * 3 resident blocks = exactly one wave
#define TILE_F4 (N_PER * DV)     // 2048 float4 = 32 KB per group tile

__device__ float        g_group_loss[G];
__device__ unsigned int g_count = 0;   // zero-init; reset by reducer each run

__global__ __launch_bounds__(256) void fused_kernel(const float* __restrict__ emb,
                                                    float* __restrict__ out) {
    extern __shared__ float4 s_buf[];   // [2][TILE_F4] = 64 KB, double buffer
    __shared__ float s_inv[N_PER];
    __shared__ float s_red[8];
    __shared__ bool  s_last;

    const int tid  = threadIdx.x;
    const int lane = tid & 31;
    const int warp = tid >> 5;

    const float4* embv  = reinterpret_cast<const float4*>(emb);
    const unsigned sbase = (unsigned)__cvta_generic_to_shared(s_buf);

    // Issue one group tile (32 KB) into buffer `buf` and commit as one group.
    auto issue_tile = [&](int g, int buf) {
        const float4* src = embv + (size_t)g * TILE_F4 + tid;
        const unsigned dst = sbase + (unsigned)(buf * TILE_F4 + tid) * 16u;
#pragma unroll
        for (int r = 0; r < N_PER; r++) {
            asm volatile("cp.async.cg.shared.global [%0], [%1], 16;\n"
                         :: "r"(dst + (unsigned)(r * DV) * 16u), "l"(src + r * DV));
        }
        asm volatile("cp.async.commit_group;\n");
    };

    int g = blockIdx.x;
    if (g < G) issue_tile(g, 0);

    int it = 0, ndone = 0;
    for (; g < G; g += NBLK, it++) {
        const int cur = it & 1;
        const int gn  = g + NBLK;
        if (gn < G) {
            issue_tile(gn, cur ^ 1);                            // prefetch next
            asm volatile("cp.async.wait_group 1;\n" ::: "memory"); // current done
        } else {
            asm volatile("cp.async.wait_group 0;\n" ::: "memory");
        }
        __syncthreads();

        const float4* t = s_buf + cur * TILE_F4;

        // phase 1: warp w computes inverse L2 norm of row w (parallel over rows)
        {
            float s = 0.0f;
#pragma unroll
            for (int k = 0; k < 8; k++) {
                float4 a = t[warp * DV + k * 32 + lane];
                s += a.x * a.x + a.y * a.y + a.z * a.z + a.w * a.w;
            }
#pragma unroll
            for (int off = 16; off > 0; off >>= 1)
                s += __shfl_xor_sync(0xFFFFFFFFu, s, off);
            if (lane == 0) s_inv[warp] = rsqrtf(fmaxf(s, 1e-24f));
        }
        __syncthreads();

        // phase 2: group-sum vector component, then ||sum||^2 block-reduce
        float sx = 0.f, sy = 0.f, sz = 0.f, sw = 0.f;
#pragma unroll
        for (int r = 0; r < N_PER; r++) {
            float4 a = t[r * DV + tid];
            const float inv = s_inv[r];
            sx = fmaf(a.x, inv, sx);
            sy = fmaf(a.y, inv, sy);
            sz = fmaf(a.z, inv, sz);
            sw = fmaf(a.w, inv, sw);
        }
        float part = sx * sx + sy * sy + sz * sz + sw * sw;
#pragma unroll
        for (int off = 16; off > 0; off >>= 1)
            part += __shfl_xor_sync(0xFFFFFFFFu, part, off);
        if (lane == 0) s_red[warp] = part;
        __syncthreads();   // also guards buffer reuse for next iteration's prefetch

        if (tid == 0) {
            float ss = 0.0f;
#pragma unroll
            for (int w = 0; w < 8; w++) ss += s_red[w];
            float mean_intra = 1.0f - (ss - (float)N_PER) * (1.0f / 56.0f);
            g_group_loss[g] = fmaxf(mean_intra - MARGIN, 0.0f);
        }
        ndone++;
    }

    // completion: last block (by group count) does the deterministic 2048->1 mean
    if (tid == 0) {
        __threadfence();
        unsigned prev = atomicAdd(&g_count, (unsigned)ndone);
        s_last = (prev + (unsigned)ndone == (unsigned)G);
        if (s_last) __threadfence();
    }
    __syncthreads();

    if (s_last) {
        float acc = 0.0f;
        for (int i = tid; i < G; i += 256) acc += g_group_loss[i];
#pragma unroll
        for (int off = 16; off > 0; off >>= 1)
            acc += __shfl_xor_sync(0xFFFFFFFFu, acc, off);
        if (lane == 0) s_red[warp] = acc;
        __syncthreads();
        if (tid == 0) {
            float s = 0.0f;
#pragma unroll
            for (int w = 0; w < 8; w++) s += s_red[w];
            out[0] = s / (float)G;
            g_count = 0;   // reset for next graph replay
        }
    }
}

extern "C" void kernel_launch(void* const* d_in, const int* in_sizes, int n_in,
                              void* d_out, int out_size) {
    const float* emb = (const float*)d_in[0];
    // d_in[1] = labels (arange(B)//8): grouping implicit in block->row mapping
    float* out = (float*)d_out;

    const int smem_bytes = 2 * TILE_F4 * (int)sizeof(float4);  // 64 KB
    cudaFuncSetAttribute(fused_kernel, cudaFuncAttributeMaxDynamicSharedMemorySize,
                         smem_bytes);
    fused_kernel<<<NBLK, 256, smem_bytes>>>(emb, out);
}

// round 6
// speedup vs baseline: 1.2212x; 1.2212x over previous
#include <cuda_runtime.h>
#include <cuda_bf16.h>

#define B       16384
#define D       1024
#define N_PER   8
#define G       (B / N_PER)      // 2048 groups == 2048 warps, one wave
#define MARGIN  0.5f
#define NPAIR   28

__device__ float        g_group_loss[G];
__device__ unsigned int g_count = 0;   // zero-init; reset by last warp each run

// One WARP per group. No shared memory, no __syncthreads. Each warp streams
// its 8x1024 fp32 tile once, accumulating all 36 pairwise dot products
// (8 squares + 28 cross terms); normalization folded in afterwards:
//   S = sum_{r<s} d_rs * rsqrt(d_rr) * rsqrt(d_ss),  loss = relu(0.5 - S/28)
__global__ void fused_kernel(const float* __restrict__ emb,
                             float* __restrict__ out) {
    const int lane = threadIdx.x & 31;
    const int g    = (blockIdx.x * blockDim.x + threadIdx.x) >> 5;  // 0..2047

    // float2 view: row stride = 512 float2, iter stride = 32 float2 (64 floats)
    const float2* p = reinterpret_cast<const float2*>(emb)
                    + (size_t)g * (N_PER * D / 2) + lane;

    float dii[N_PER];
    float dij[NPAIR];
#pragma unroll
    for (int r = 0; r < N_PER; r++) dii[r] = 0.0f;
#pragma unroll
    for (int q = 0; q < NPAIR; q++) dij[q] = 0.0f;

#pragma unroll 4
    for (int k = 0; k < 16; k++) {
        float2 a[N_PER];
#pragma unroll
        for (int r = 0; r < N_PER; r++)
            a[r] = p[r * (D / 2) + k * 32];
#pragma unroll
        for (int r = 0; r < N_PER; r++) {
            dii[r] = fmaf(a[r].x, a[r].x, dii[r]);
            dii[r] = fmaf(a[r].y, a[r].y, dii[r]);
        }
        int q = 0;
#pragma unroll
        for (int r = 0; r < N_PER; r++)
#pragma unroll
            for (int s = r + 1; s < N_PER; s++, q++) {
                dij[q] = fmaf(a[r].x, a[s].x, dij[q]);
                dij[q] = fmaf(a[r].y, a[s].y, dij[q]);
            }
    }

    // Warp-reduce all 36 accumulators (xor butterfly -> value in every lane)
#pragma unroll
    for (int r = 0; r < N_PER; r++)
#pragma unroll
        for (int off = 16; off > 0; off >>= 1)
            dii[r] += __shfl_xor_sync(0xFFFFFFFFu, dii[r], off);
#pragma unroll
    for (int q = 0; q < NPAIR; q++)
#pragma unroll
        for (int off = 16; off > 0; off >>= 1)
            dij[q] += __shfl_xor_sync(0xFFFFFFFFu, dij[q], off);

    bool last = false;
    if (lane == 0) {
        float w[N_PER];
#pragma unroll
        for (int r = 0; r < N_PER; r++)
            w[r] = rsqrtf(fmaxf(dii[r], 1e-24f));
        float S = 0.0f;
        int q = 0;
#pragma unroll
        for (int r = 0; r < N_PER; r++)
#pragma unroll
            for (int s = r + 1; s < N_PER; s++, q++)
                S += dij[q] * w[r] * w[s];
        // mean_intra - margin = (1 - S/28) - 0.5 = 0.5 - S/28
        g_group_loss[g] = fmaxf(0.5f - S * (1.0f / (float)NPAIR), 0.0f);
        __threadfence();
        unsigned done = atomicAdd(&g_count, 1u);
        last = (done == (unsigned)(G - 1));
    }
    last = __shfl_sync(0xFFFFFFFFu, last ? 1 : 0, 0) != 0;

    // Last warp: deterministic 2048 -> 1 mean (fixed summation order per lane)
    if (last) {
        if (lane == 0) __threadfence();
        __syncwarp();
        float acc = 0.0f;
        for (int i = lane; i < G; i += 32) acc += g_group_loss[i];
#pragma unroll
        for (int off = 16; off > 0; off >>= 1)
            acc += __shfl_xor_sync(0xFFFFFFFFu, acc, off);
        if (lane == 0) {
            out[0] = acc / (float)G;
            g_count = 0;   // reset for next graph replay
        }
    }
}

extern "C" void kernel_launch(void* const* d_in, const int* in_sizes, int n_in,
                              void* d_out, int out_size) {
    const float* emb = (const float*)d_in[0];
    // d_in[1] = labels (arange(B)//8): grouping implicit in warp->rows map
    float* out = (float*)d_out;
    // 2048 warps total: 512 blocks x 128 threads (4 warps/block)
    fused_kernel<<<512, 128>>>(emb, out);
}